// round 16
// baseline (speedup 1.0000x reference)
#include <cuda_runtime.h>
#include <cstdint>

#define NPLANES 16384          // 64*256
#define HM 50
#define WM 50
#define HH 56
#define NTOT 51380224          // 64*256*56*56
#define NVEC (NTOT/4)          // 12845056 float4s (x / out)
#define NVEC2 (NVEC/2)
#define PLANE_ELEMS (HM*WM)    // 2500
#define MV4 (NPLANES*PLANE_ELEMS/4)   // 10,240,000 mask float4s = 1024 * 10000
#define SCAN_BLOCKS (MV4/1024)        // 10000
#define DIL_BLOCKS (NPLANES/8)        // 2048

typedef unsigned long long ull;

__device__ ull g_raw[NPLANES * HM];      // 6.5 MB; invariant: all-zero at entry
                                         // (static init + re-zeroed by dilate)
__device__ ull g_blocked[NPLANES * HH];  // 7.3 MB dilated row masks
__device__ ull g_count = 0ULL;           // invariant: 0 at entry
__device__ unsigned g_done = 0u;         // ticket, reset each launch
__device__ float g_scale;

// Pure streaming scan: 4 unconditional front-batched LDG.128 per thread
// (MLP=4, no branch between loads), min-tree, then a rare global atomicOr
// scatter (horizontal 7-dilation fused via 0x7F << col). No smem, no syncs.
__global__ __launch_bounds__(256) void scan_kernel(const float4* __restrict__ mu4) {
    const float gamma = (float)(0.1 / 49.0 * 3136.0 / 2500.0);
    const int base = blockIdx.x * 1024 + threadIdx.x;

    float4 v0 = __ldcs(&mu4[base]);
    float4 v1 = __ldcs(&mu4[base + 256]);
    float4 v2 = __ldcs(&mu4[base + 512]);
    float4 v3 = __ldcs(&mu4[base + 768]);

    float m01 = fminf(fminf(fminf(v0.x, v0.y), fminf(v0.z, v0.w)),
                      fminf(fminf(v1.x, v1.y), fminf(v1.z, v1.w)));
    float m23 = fminf(fminf(fminf(v2.x, v2.y), fminf(v2.z, v2.w)),
                      fminf(fminf(v3.x, v3.y), fminf(v3.z, v3.w)));

    if (fminf(m01, m23) < gamma) {                 // rare (~2.6% of threads)
        const float4 vs[4] = {v0, v1, v2, v3};
        #pragma unroll
        for (int c = 0; c < 4; c++) {
            int eb = (base + c * 256) * 4;
            #pragma unroll
            for (int j = 0; j < 4; j++) {
                float f = (j == 0) ? vs[c].x : (j == 1) ? vs[c].y
                        : (j == 2) ? vs[c].z : vs[c].w;
                if (f < gamma) {
                    int e     = eb + j;
                    int plane = e / PLANE_ELEMS;
                    int rem   = e - plane * PLANE_ELEMS;
                    int r     = rem / WM;
                    int cc    = rem - r * WM;
                    atomicOr(&g_raw[plane * HM + r], 0x7FULL << cc);
                }
            }
        }
    }
}

// One warp per plane: vertical OR over [h-6, h] -> g_blocked, re-zero g_raw
// (restores the replay invariant), popcount + count; last block finalizes
// g_scale and resets the counters.
__global__ __launch_bounds__(256) void dilate_kernel() {
    __shared__ ull rows[8][HM];
    __shared__ int wsum[8];

    const int tid  = threadIdx.x;
    const int warp = tid >> 5;
    const int lane = tid & 31;
    const int plane = blockIdx.x * 8 + warp;

    ull* praw = &g_raw[(size_t)plane * HM];
    rows[warp][lane] = praw[lane];
    if (lane < HM - 32) rows[warp][lane + 32] = praw[lane + 32];
    __syncwarp();
    praw[lane] = 0ULL;
    if (lane < HM - 32) praw[lane + 32] = 0ULL;

    int cnt = 0;
    #pragma unroll
    for (int hh = 0; hh < 2; hh++) {
        int h = lane + hh * 32;
        if (h < HH) {
            int a = h - 6; if (a < 0) a = 0;
            int b = h;     if (b > HM - 1) b = HM - 1;
            ull o = 0ULL;
            for (int r = a; r <= b; r++) o |= rows[warp][r];
            g_blocked[(size_t)plane * HH + h] = o;
            cnt += __popcll(o);
        }
    }
    #pragma unroll
    for (int off = 16; off; off >>= 1)
        cnt += __shfl_down_sync(0xFFFFFFFFu, cnt, off);
    if (lane == 0) wsum[warp] = cnt;
    __syncthreads();

    if (tid == 0) {
        int s = 0;
        #pragma unroll
        for (int w = 0; w < 8; w++) s += wsum[w];
        atomicAdd(&g_count, (ull)s);
        __threadfence();
        unsigned ticket = atomicAdd(&g_done, 1u);
        if (ticket == DIL_BLOCKS - 1) {
            ull c = atomicAdd(&g_count, 0ULL);
            g_scale = (float)((double)NTOT / (double)(NTOT - (long long)c));
            g_count = 0ULL;
            g_done  = 0u;
        }
    }
}

// Elementwise apply (proven R4 form, 76% DRAM): out = x * (1-blocked) * scale.
__global__ __launch_bounds__(256) void apply_kernel(const float4* __restrict__ x4,
                                                    float4* __restrict__ out4) {
    const int v0 = blockIdx.x * blockDim.x + threadIdx.x;
    const float s = g_scale;

    #pragma unroll
    for (int half = 0; half < 2; half++) {
        int v = v0 + half * NVEC2;
        int rowg = v / 14;               // global row == plane*56 + h
        int c4   = v - rowg * 14;
        unsigned bits = (unsigned)(g_blocked[rowg] >> (c4 * 4)) & 0xFu;

        float4 xi = __ldcs(&x4[v]);
        float4 o;
        o.x = (bits & 1u) ? 0.0f : xi.x * s;
        o.y = (bits & 2u) ? 0.0f : xi.y * s;
        o.z = (bits & 4u) ? 0.0f : xi.z * s;
        o.w = (bits & 8u) ? 0.0f : xi.w * s;
        __stcs(&out4[v], o);
    }
}

extern "C" void kernel_launch(void* const* d_in, const int* in_sizes, int n_in,
                              void* d_out, int out_size) {
    const float* x      = (const float*)d_in[0];
    const float* mask_u = (const float*)d_in[1];
    float* out          = (float*)d_out;

    scan_kernel<<<SCAN_BLOCKS, 256>>>((const float4*)mask_u);
    dilate_kernel<<<DIL_BLOCKS, 256>>>();
    apply_kernel<<<NVEC2 / 256, 256>>>((const float4*)x, (float4*)out);
}